// round 11
// baseline (speedup 1.0000x reference)
#include <cuda_runtime.h>
#include <cuda_fp16.h>
#include <cstdint>
#include <math.h>

#define NN_ 64
#define PP_ 1024
#define EE_ 512
#define HH_ 8
#define MBIG (NN_*PP_)   // 65536

// dynamic smem: 3 stages x (A 8192 + B 8192 halfs) = 49152 halfs = 98304 B
#define SMEM_BYTES 98304

// ---------------- scratch (__device__ globals; no allocs allowed) ----------
// Packed-A (fp16), per 128-row panel: [K/16][8 rt][32 lane][8 halfs]
//   lane(g=l>>2,t=l&3): {A[rt*16+g][16k+2t],[+1], A[+8 row][2t],[+1], A[g][2t+8],[+9], A[g+8][2t+8],[+9]}
// Packed-B (fp16): [K/16][nb][32 lane][4 halfs]: {B[nb*8+g][16k+2t],[+1],[2t+8],[+9]}
__device__ __half g_xa [(size_t)512*65536];   // x packed-A, 512 panels        64MB
__device__ __half g_vp [(size_t)EE_*EE_];     // V packed-B  [32 k16][64 nb]   0.5MB
__device__ __half g_wp [(size_t)EE_*EE_];     // W^T packed-B                  0.5MB
__device__ __half g_ap [(size_t)64*131072];   // alpha_mat packed-A, 64 panels 16MB
__device__ __half g_wsp[(size_t)512*65536];   // ws packed-B per (n,h) slab    64MB
__device__ __half g_yp [(size_t)512*65536];   // y packed-A, 512 panels        64MB

// ---------------- helpers --------------------------------------------------
__device__ __forceinline__ uint32_t smem_u32(const void* p){
    uint32_t a;
    asm("{ .reg .u64 t; cvta.to.shared.u64 t, %1; cvt.u32.u64 %0, t; }":"=r"(a):"l"(p));
    return a;
}
__device__ __forceinline__ uint32_t f2h2(float a, float b){
    __half2 h = __floats2half2_rn(a, b);
    return *(uint32_t*)&h;
}
__device__ __forceinline__ float log_cosh_f(float v){
    float ax = fabsf(v);
    return ax + log1pf(expf(-2.0f*ax)) - 0.6931471805599453f;
}
__device__ __forceinline__ void mma_f16(float c[4], uint4 a, uint2 b)
{
    asm volatile("mma.sync.aligned.m16n8k16.row.col.f32.f16.f16.f32 "
        "{%0,%1,%2,%3}, {%4,%5,%6,%7}, {%8,%9}, {%0,%1,%2,%3};"
        : "+f"(c[0]), "+f"(c[1]), "+f"(c[2]), "+f"(c[3])
        : "r"(a.x), "r"(a.y), "r"(a.z), "r"(a.w), "r"(b.x), "r"(b.y));
}

// ---------------------------------------------------------------------------
// Mainloop: acc(128x128) += A(128xK) * B(128xK)^T, fp16 fragment-major packed.
// Tile BK=64 (4 k16 steps). 3-stage cp.async pipeline, one sync per tile.
// 256 thr, warps 2(M)x4(N), warp tile 64x32. 64 MMAs + 32 LDS per warp-tile.
// A slab/tile: 8192 halfs contiguous at Ap + tt*8192.
// B per k16: nb 0..7 from B0, 8..15 from B1; per-k16 stride bstride (halfs).
// ---------------------------------------------------------------------------
__device__ __forceinline__ void gemm_loop(
    const __half* __restrict__ Ap,
    const __half* __restrict__ B0, const __half* __restrict__ B1,
    size_t bstride, int kt, __half* __restrict__ sm, float acc[4][4][4])
{
    const int tid = threadIdx.x, wid = tid >> 5, lane = tid & 31;
    const int wrt = (wid >> 2) * 4;   // A rt base: 0 or 4
    const int wnb = (wid & 3) * 4;    // B nb base: 0,4,8,12

    auto load_tile = [&](int tt, int buf){
        __half* dA = sm + buf*16384;
        __half* dB = dA + 8192;
        const __half* As = Ap + (size_t)tt*8192;
        #pragma unroll
        for (int i = 0; i < 4; i++) {                 // A: 1024 x 16B chunks
            int c = tid + i*256;
            uint32_t dst = smem_u32(dA + c*8);
            asm volatile("cp.async.cg.shared.global [%0], [%1], 16;"
                         :: "r"(dst), "l"(As + c*8));
        }
        #pragma unroll
        for (int i = 0; i < 4; i++) {                 // B: 1024 x 16B chunks
            int c = tid + i*256;
            int k16s = c >> 8, r = c & 255;
            int nb = r >> 4, lp = r & 15;
            const __half* src = ((nb & 8) ? B1 : B0)
                              + (size_t)(tt*4 + k16s)*bstride + (nb & 7)*128 + lp*8;
            uint32_t dst = smem_u32(dB + k16s*2048 + nb*128 + lp*8);
            asm volatile("cp.async.cg.shared.global [%0], [%1], 16;"
                         :: "r"(dst), "l"(src));
        }
        asm volatile("cp.async.commit_group;" ::: "memory");
    };

    load_tile(0, 0);
    if (kt > 1) load_tile(1, 1);

    for (int tt = 0; tt < kt; tt++) {
        const int cur = tt % 3;
        asm volatile("cp.async.wait_group 1;" ::: "memory");
        __syncthreads();
        if (tt + 2 < kt) load_tile(tt + 2, (tt + 2) % 3);

        const uint4* fA = (const uint4*)(sm + cur*16384);
        const uint2* fB = (const uint2*)(sm + cur*16384 + 8192);
        #pragma unroll
        for (int ks = 0; ks < 4; ks++) {
            uint4 a[4]; uint2 b[4];
            #pragma unroll
            for (int tm = 0; tm < 4; tm++)
                a[tm] = fA[ks*256 + (wrt + tm)*32 + lane];
            #pragma unroll
            for (int tn = 0; tn < 4; tn++)
                b[tn] = fB[ks*512 + (wnb + tn)*32 + lane];
            #pragma unroll
            for (int tm = 0; tm < 4; tm++)
                #pragma unroll
                for (int tn = 0; tn < 4; tn++)
                    mma_f16(acc[tm][tn], a[tm], b[tn]);
        }
    }
}

// ---------------------------------------------------------------------------
// Stage 1: ws[n,p,hr] = x @ V^T; epilogue writes packed-B fp16 slabs g_wsp.
// grid (x: 4 hr-tiles of 128, y: 512 m-tiles of 128)
// ---------------------------------------------------------------------------
__global__ __launch_bounds__(256, 2) void k_stage1()
{
    extern __shared__ __half smh[];
    const int bn = blockIdx.x * 128;
    const int bm = blockIdx.y * 128;
    float acc[4][4][4] = {};
    const __half* b0 = g_vp + (bn >> 3) * 128;
    gemm_loop(g_xa + (size_t)(bm >> 7)*65536, b0, b0 + 1024, 8192, 8, smh, acc);

    __syncthreads();
    float* Ts = (float*)smh;   // Ts[hrloc][ploc], stride 132 (transposed C)
    const int tid = threadIdx.x, wid = tid >> 5, lane = tid & 31;
    const int wm = (wid >> 2) * 64, wn = (wid & 3) * 32;
    const int gg = lane >> 2, tq = lane & 3;
    #pragma unroll
    for (int tm = 0; tm < 4; tm++)
        #pragma unroll
        for (int tn = 0; tn < 4; tn++) {
            int m0 = wm + tm*16 + gg, n0 = wn + tn*8 + 2*tq;
            Ts[(n0    )*132 + m0    ] = acc[tm][tn][0];
            Ts[(n0 + 1)*132 + m0    ] = acc[tm][tn][1];
            Ts[(n0    )*132 + m0 + 8] = acc[tm][tn][2];
            Ts[(n0 + 1)*132 + m0 + 8] = acc[tm][tn][3];
        }
    __syncthreads();

    const int n = bm >> 10, pbase = bm & 1023;
    #pragma unroll
    for (int i = 0; i < 16; i++) {
        int u = tid + i*256;
        int k16rel = u >> 9, rest = u & 511;
        int nbg = rest >> 5, l = rest & 31;
        int g = l >> 2, t = l & 3;
        int hrloc = nbg*8 + g;
        int hrAbs = bn + hrloc;
        const float* ts = Ts + hrloc*132 + k16rel*16 + 2*t;
        uint2 v;
        v.x = f2h2(ts[0], ts[1]);
        v.y = f2h2(ts[8], ts[9]);
        size_t dst = (size_t)(n*8 + (hrAbs >> 6))*65536
                   + (size_t)((pbase >> 4) + k16rel)*1024
                   + ((hrAbs >> 3) & 7)*128 + l*4;
        *(uint2*)(g_wsp + dst) = v;
    }
}

// ---------------------------------------------------------------------------
// Stage 2: y[n,p,h*64+r] = alpha_mat @ ws; epilogue writes packed-A fp16 g_yp.
// Two n per block (B halves). grid (x: 32 n-pairs, y: h*8 + ptile)
// ---------------------------------------------------------------------------
__global__ __launch_bounds__(256, 2) void k_stage2()
{
    extern __shared__ __half smh[];
    const int n0 = blockIdx.x * 2;
    const int h  = blockIdx.y >> 3;
    const int pt = blockIdx.y & 7;
    float acc[4][4][4] = {};
    gemm_loop(g_ap + (size_t)(h*8 + pt)*131072,
              g_wsp + (size_t)(n0*8 + h)*65536,
              g_wsp + (size_t)((n0+1)*8 + h)*65536,
              1024, 16, smh, acc);

    __syncthreads();
    float* S = (float*)smh;   // S[ploc][col], stride 132; col = half*64 + r
    const int tid = threadIdx.x, wid = tid >> 5, lane = tid & 31;
    const int wm = (wid >> 2) * 64, wn = (wid & 3) * 32;
    const int gg = lane >> 2, tq = lane & 3;
    #pragma unroll
    for (int tm = 0; tm < 4; tm++)
        #pragma unroll
        for (int tn = 0; tn < 4; tn++) {
            int m0 = wm + tm*16 + gg, c0 = wn + tn*8 + 2*tq;
            S[(m0    )*132 + c0    ] = acc[tm][tn][0];
            S[(m0    )*132 + c0 + 1] = acc[tm][tn][1];
            S[(m0 + 8)*132 + c0    ] = acc[tm][tn][2];
            S[(m0 + 8)*132 + c0 + 1] = acc[tm][tn][3];
        }
    __syncthreads();

    #pragma unroll
    for (int i = 0; i < 8; i++) {
        int u = tid + i*256;
        int half_ = u >> 10, v_ = u & 1023;
        int k16rel = v_ >> 8, rt = (v_ >> 5) & 7, l = v_ & 31;
        int g = l >> 2, t = l & 3;
        int row0 = rt*16 + g;
        const float* s0 = S + row0*132 + half_*64 + k16rel*16 + 2*t;
        const float* s1 = s0 + 8*132;
        uint4 v;
        v.x = f2h2(s0[0], s0[1]);
        v.y = f2h2(s1[0], s1[1]);
        v.z = f2h2(s0[8], s0[9]);
        v.w = f2h2(s1[8], s1[9]);
        size_t dst = (size_t)((n0 + half_)*8 + pt)*65536
                   + (size_t)(h*4 + k16rel)*2048 + rt*256 + l*8;
        *(uint4*)(g_yp + dst) = v;
    }
}

// ---------------------------------------------------------------------------
// Stage 3: out[m][e] = log_cosh( y @ W + b )
// grid (x: 4 e-tiles of 128, y: 512 m-tiles of 128)
// ---------------------------------------------------------------------------
__global__ __launch_bounds__(256, 2) void k_stage3(const float* __restrict__ bias,
                                                   float* __restrict__ out)
{
    extern __shared__ __half smh[];
    const int bn = blockIdx.x * 128;
    const int bm = blockIdx.y * 128;
    float acc[4][4][4] = {};
    const __half* b0 = g_wp + (bn >> 3) * 128;
    gemm_loop(g_yp + (size_t)(bm >> 7)*65536, b0, b0 + 1024, 8192, 8, smh, acc);

    const int tid = threadIdx.x, wid = tid >> 5, lane = tid & 31;
    const int wm = (wid >> 2) * 64, wn = (wid & 3) * 32;
    const int gg = lane >> 2, tq = lane & 3;
    #pragma unroll
    for (int tn = 0; tn < 4; tn++) {
        int n0 = wn + tn*8 + 2*tq;
        float bb0 = bias[bn + n0], bb1 = bias[bn + n0 + 1];
        #pragma unroll
        for (int tm = 0; tm < 4; tm++) {
            int m0 = bm + wm + tm*16 + gg;
            float2 v0 = make_float2(log_cosh_f(acc[tm][tn][0] + bb0),
                                    log_cosh_f(acc[tm][tn][1] + bb1));
            float2 v1 = make_float2(log_cosh_f(acc[tm][tn][2] + bb0),
                                    log_cosh_f(acc[tm][tn][3] + bb1));
            *(float2*)(out + (size_t)(m0    )*EE_ + bn + n0) = v0;
            *(float2*)(out + (size_t)(m0 + 8)*EE_ + bn + n0) = v1;
        }
    }
}

// ---------------------------------------------------------------------------
// Prep: pack operands into fp16 fragment-major layouts
// ---------------------------------------------------------------------------
__global__ void k_pack_x(const float* __restrict__ x)   // grid (512 panels, 8 kslabs)
{
    __shared__ float S[128*68];
    const int panel = blockIdx.x, kslab = blockIdx.y;   // kslab covers 64 cols (4 k16)
    const int tid = threadIdx.x;
    #pragma unroll
    for (int i = 0; i < 8; i++) {
        int c = tid + i*256;               // 2048 x 16B chunks
        int row = c >> 4, seg = c & 15;
        float4 v = *(const float4*)(x + (size_t)(panel*128 + row)*512 + kslab*64 + seg*4);
        *(float4*)(S + row*68 + seg*4) = v;
    }
    __syncthreads();
    #pragma unroll
    for (int i = 0; i < 4; i++) {
        int u = tid + i*256;
        int k16 = u >> 8, rt = (u >> 5) & 7, l = u & 31;
        int g = l >> 2, t = l & 3;
        const float* s0 = S + (rt*16 + g)*68 + k16*16 + 2*t;
        const float* s1 = s0 + 8*68;
        uint4 v;
        v.x = f2h2(s0[0], s0[1]);
        v.y = f2h2(s1[0], s1[1]);
        v.z = f2h2(s0[8], s0[9]);
        v.w = f2h2(s1[8], s1[9]);
        *(uint4*)(g_xa + (size_t)panel*65536 + (size_t)(kslab*4 + k16)*2048
                  + rt*256 + l*8) = v;
    }
}

__global__ void k_pack_v(const float* __restrict__ V)   // grid (32 k16, 8)
{
    int k16 = blockIdx.x, nb = blockIdx.y*8 + (threadIdx.x >> 5), l = threadIdx.x & 31;
    int g = l >> 2, t = l & 3;
    const float* r = V + (size_t)(nb*8 + g)*512 + k16*16 + 2*t;
    uint2 v;
    v.x = f2h2(r[0], r[1]);
    v.y = f2h2(r[8], r[9]);
    *(uint2*)(g_vp + k16*8192 + nb*128 + l*4) = v;
}

__global__ void k_pack_w(const float* __restrict__ W)   // packs W^T; grid (32, 8)
{
    int k16 = blockIdx.x, nb = blockIdx.y*8 + (threadIdx.x >> 5), l = threadIdx.x & 31;
    int g = l >> 2, t = l & 3;
    int e = nb*8 + g, k = k16*16 + 2*t;
    uint2 v;
    v.x = f2h2(W[(size_t)(k    )*512 + e], W[(size_t)(k + 1)*512 + e]);
    v.y = f2h2(W[(size_t)(k + 8)*512 + e], W[(size_t)(k + 9)*512 + e]);
    *(uint2*)(g_wp + k16*8192 + nb*128 + l*4) = v;
}

__global__ void k_pack_amat(const float* __restrict__ alpha)  // grid (8 k16c, 8 pt, 8 h)
{
    __shared__ float as_[1024];
    const int k16c = blockIdx.x, pt = blockIdx.y, h = blockIdx.z;
    const int tid = threadIdx.x;
    for (int i = tid; i < 1024; i += 256) as_[i] = alpha[h*1024 + i];
    __syncthreads();
    #pragma unroll
    for (int i = 0; i < 8; i++) {
        int u = tid + i*256;
        int k16r = u >> 8, rt = (u >> 5) & 7, l = u & 31;
        int g = l >> 2, t = l & 3;
        int j = (k16c*8 + k16r)*16 + 2*t;
        int p = pt*128 + rt*16 + g;
        uint4 v;
        v.x = f2h2(as_[(j     - p) & 1023], as_[(j + 1 - p) & 1023]);
        v.y = f2h2(as_[(j - 8 - p) & 1023], as_[(j - 7 - p) & 1023]);
        v.z = f2h2(as_[(j + 8 - p) & 1023], as_[(j + 9 - p) & 1023]);
        v.w = f2h2(as_[(j     - p) & 1023], as_[(j + 1 - p) & 1023]);
        *(uint4*)(g_ap + (size_t)(h*8 + pt)*131072
                  + (size_t)(k16c*8 + k16r)*2048 + rt*256 + l*8) = v;
    }
}

// ---------------------------------------------------------------------------
extern "C" void kernel_launch(void* const* d_in, const int* in_sizes, int n_in,
                              void* d_out, int out_size)
{
    const float* x     = (const float*)d_in[0];
    const float* alpha = (const float*)d_in[1];
    const float* V     = (const float*)d_in[2];
    const float* W     = (const float*)d_in[3];
    const float* b     = (const float*)d_in[4];
    float* out = (float*)d_out;

    cudaFuncSetAttribute(k_stage1, cudaFuncAttributeMaxDynamicSharedMemorySize, SMEM_BYTES);
    cudaFuncSetAttribute(k_stage2, cudaFuncAttributeMaxDynamicSharedMemorySize, SMEM_BYTES);
    cudaFuncSetAttribute(k_stage3, cudaFuncAttributeMaxDynamicSharedMemorySize, SMEM_BYTES);

    // Prep: pack all operands to fragment-major fp16 layouts
    k_pack_x   <<<dim3(512, 8), 256>>>(x);
    k_pack_v   <<<dim3(32, 8),  256>>>(V);
    k_pack_w   <<<dim3(32, 8),  256>>>(W);
    k_pack_amat<<<dim3(8, 8, 8), 256>>>(alpha);

    // Stage 1: ws = (x @ V^T), packed-B out     M=65536 N=512 K=512
    k_stage1<<<dim3(4, 512), 256, SMEM_BYTES>>>();
    // Stage 2: y = alpha_mat @ ws, packed-A out M=1024 N=128 K=1024 (x64 batches)
    k_stage2<<<dim3(32, 64), 256, SMEM_BYTES>>>();
    // Stage 3: out = log_cosh(y @ W + b)        M=65536 N=512 K=512
    k_stage3<<<dim3(4, 512), 256, SMEM_BYTES>>>(b, out);
}

// round 12
// speedup vs baseline: 1.1331x; 1.1331x over previous
#include <cuda_runtime.h>
#include <cuda_fp16.h>
#include <cstdint>
#include <math.h>

#define NN_ 64
#define PP_ 1024
#define EE_ 512
#define HH_ 8
#define MBIG (NN_*PP_)

#define SMEM_BYTES 98304   // 3 stages x (A 8192 + B 8192 halfs)

// ---------------- scratch ---------------------------------------------------
__device__ __half g_xa [(size_t)512*65536];   // x packed-A
__device__ __half g_vp [(size_t)EE_*EE_];     // V packed-B
__device__ __half g_wp [(size_t)EE_*EE_];     // W^T packed-B
__device__ __half g_wsp[(size_t)512*65536];   // ws packed-B per (n,h)
__device__ __half g_wc [(size_t)512*65536];   // W-hat slabs per (n,h)
__device__ __half g_dp [(size_t)8*229376];    // D-hat packed-A panels per h
__device__ float  g_P  [(size_t)256*8*16384]; // products fp32 [(bp*8+h)][c][i][col]
__device__ __half g_yp [(size_t)512*65536];   // y packed-A

// DFT weight rows: {1, (-1)^d, cos(pi d/4), sin(pi d/4), cos(pi d/2), sin(pi d/2), cos(3pi d/4), sin(3pi d/4)}
#define C7 0.70710678118654752f
__constant__ float DW[8][8] = {
 {1,1,1,1,1,1,1,1}, {1,-1,1,-1,1,-1,1,-1},
 {1,C7,0,-C7,-1,-C7,0,C7}, {0,C7,1,C7,0,-C7,-1,-C7},
 {1,0,-1,0,1,0,-1,0}, {0,1,0,-1,0,1,0,-1},
 {1,-C7,0,C7,-1,C7,0,-C7}, {0,C7,-1,C7,0,-C7,1,-C7}};
// combine: y_pt = sum_c MC[pt][c] * P_c ; comps {P0,P4,P1r,P1i,P2r,P2i,P3r,P3i}
#define Q 0.17677669529663687f
__constant__ float MC[8][8] = {
 {.125f,.125f,.25f,0,.25f,0,.25f,0},
 {.125f,-.125f,Q,-Q,0,-.25f,-Q,-Q},
 {.125f,.125f,0,-.25f,-.25f,0,0,.25f},
 {.125f,-.125f,-Q,-Q,0,.25f,Q,-Q},
 {.125f,.125f,-.25f,0,.25f,0,-.25f,0},
 {.125f,-.125f,-Q,Q,0,-.25f,Q,Q},
 {.125f,.125f,0,.25f,-.25f,0,0,-.25f},
 {.125f,-.125f,Q,Q,0,.25f,-Q,Q}};
__constant__ int BK16[28] = {0,4,8,12,16,20,24,28,16,20,24,28,
                             32,36,40,44,32,36,40,44,48,52,56,60,48,52,56,60};
__constant__ int DEND[28] = {-1,0,-1,1,-1,-1,-1,2,-1,-1,-1,3,
                             -1,-1,-1,4,-1,-1,-1,5,-1,-1,-1,6,-1,-1,-1,7};
__constant__ int VID[28]  = {0,0,1,1,2,2,3,3,3,3,2,2,4,4,5,5,5,5,4,4,6,6,7,7,7,7,6,6};
__constant__ float SGN[28]= {1,1,1,1,1,1,-1,-1,1,1,1,1,1,1,-1,-1,1,1,1,1,1,1,-1,-1,1,1,1,1};

// ---------------- helpers ---------------------------------------------------
__device__ __forceinline__ uint32_t smem_u32(const void* p){
    uint32_t a;
    asm("{ .reg .u64 t; cvta.to.shared.u64 t, %1; cvt.u32.u64 %0, t; }":"=r"(a):"l"(p));
    return a;
}
__device__ __forceinline__ uint32_t f2h2(float a, float b){
    __half2 h = __floats2half2_rn(a, b);
    return *(uint32_t*)&h;
}
__device__ __forceinline__ float log_cosh_f(float v){
    float ax = fabsf(v);
    return ax + log1pf(expf(-2.0f*ax)) - 0.6931471805599453f;
}
__device__ __forceinline__ void mma_f16(float c[4], uint4 a, uint2 b)
{
    asm volatile("mma.sync.aligned.m16n8k16.row.col.f32.f16.f16.f32 "
        "{%0,%1,%2,%3}, {%4,%5,%6,%7}, {%8,%9}, {%0,%1,%2,%3};"
        : "+f"(c[0]), "+f"(c[1]), "+f"(c[2]), "+f"(c[3])
        : "r"(a.x), "r"(a.y), "r"(a.z), "r"(a.w), "r"(b.x), "r"(b.y));
}

// ---------------- shared mainloop for stages 1/3 ----------------------------
__device__ __forceinline__ void gemm_loop(
    const __half* __restrict__ Ap,
    const __half* __restrict__ B0, const __half* __restrict__ B1,
    size_t bstride, int kt, __half* __restrict__ sm, float acc[4][4][4])
{
    const int tid = threadIdx.x, wid = tid >> 5, lane = tid & 31;
    const int wrt = (wid >> 2) * 4, wnb = (wid & 3) * 4;

    auto load_tile = [&](int tt, int buf){
        __half* dA = sm + buf*16384;
        __half* dB = dA + 8192;
        const __half* As = Ap + (size_t)tt*8192;
        #pragma unroll
        for (int i = 0; i < 4; i++) {
            int c = tid + i*256;
            uint32_t dst = smem_u32(dA + c*8);
            asm volatile("cp.async.cg.shared.global [%0], [%1], 16;"
                         :: "r"(dst), "l"(As + c*8));
        }
        #pragma unroll
        for (int i = 0; i < 4; i++) {
            int c = tid + i*256;
            int k16s = c >> 8, r = c & 255, nb = r >> 4, lp = r & 15;
            const __half* src = ((nb & 8) ? B1 : B0)
                              + (size_t)(tt*4 + k16s)*bstride + (nb & 7)*128 + lp*8;
            uint32_t dst = smem_u32(dB + k16s*2048 + nb*128 + lp*8);
            asm volatile("cp.async.cg.shared.global [%0], [%1], 16;"
                         :: "r"(dst), "l"(src));
        }
        asm volatile("cp.async.commit_group;" ::: "memory");
    };

    load_tile(0, 0);
    if (kt > 1) load_tile(1, 1);

    for (int tt = 0; tt < kt; tt++) {
        const int cur = tt % 3;
        if (tt + 1 < kt) asm volatile("cp.async.wait_group 1;" ::: "memory");
        else             asm volatile("cp.async.wait_group 0;" ::: "memory");
        __syncthreads();
        if (tt + 2 < kt) load_tile(tt + 2, (tt + 2) % 3);

        const uint4* fA = (const uint4*)(sm + cur*16384);
        const uint2* fB = (const uint2*)(sm + cur*16384 + 8192);
        #pragma unroll
        for (int ks = 0; ks < 4; ks++) {
            uint4 a[4]; uint2 b[4];
            #pragma unroll
            for (int tm = 0; tm < 4; tm++) a[tm] = fA[ks*256 + (wrt + tm)*32 + lane];
            #pragma unroll
            for (int tn = 0; tn < 4; tn++) b[tn] = fB[ks*512 + (wnb + tn)*32 + lane];
            #pragma unroll
            for (int tm = 0; tm < 4; tm++)
                #pragma unroll
                for (int tn = 0; tn < 4; tn++)
                    mma_f16(acc[tm][tn], a[tm], b[tn]);
        }
    }
}

// ---------------- Stage 1: ws = x @ V^T -> packed-B slabs -------------------
__global__ __launch_bounds__(256, 2) void k_stage1()
{
    extern __shared__ __half smh[];
    const int bn = blockIdx.x * 128, bm = blockIdx.y * 128;
    float acc[4][4][4] = {};
    const __half* b0 = g_vp + (bn >> 3) * 128;
    gemm_loop(g_xa + (size_t)(bm >> 7)*65536, b0, b0 + 1024, 8192, 8, smh, acc);

    __syncthreads();
    float* Ts = (float*)smh;
    const int tid = threadIdx.x, wid = tid >> 5, lane = tid & 31;
    const int wm = (wid >> 2) * 64, wn = (wid & 3) * 32;
    const int gg = lane >> 2, tq = lane & 3;
    #pragma unroll
    for (int tm = 0; tm < 4; tm++)
        #pragma unroll
        for (int tn = 0; tn < 4; tn++) {
            int m0 = wm + tm*16 + gg, n0 = wn + tn*8 + 2*tq;
            Ts[(n0    )*132 + m0    ] = acc[tm][tn][0];
            Ts[(n0 + 1)*132 + m0    ] = acc[tm][tn][1];
            Ts[(n0    )*132 + m0 + 8] = acc[tm][tn][2];
            Ts[(n0 + 1)*132 + m0 + 8] = acc[tm][tn][3];
        }
    __syncthreads();

    const int n = bm >> 10, pbase = bm & 1023;
    #pragma unroll
    for (int i = 0; i < 16; i++) {
        int u = tid + i*256;
        int k16rel = u >> 9, rest = u & 511;
        int nbg = rest >> 5, l = rest & 31, g = l >> 2, t = l & 3;
        int hrloc = nbg*8 + g, hrAbs = bn + hrloc;
        const float* ts = Ts + hrloc*132 + k16rel*16 + 2*t;
        uint2 v;
        v.x = f2h2(ts[0], ts[1]);
        v.y = f2h2(ts[8], ts[9]);
        size_t dst = (size_t)(n*8 + (hrAbs >> 6))*65536
                   + (size_t)((pbase >> 4) + k16rel)*1024
                   + ((hrAbs >> 3) & 7)*128 + l*4;
        *(uint2*)(g_wsp + dst) = v;
    }
}

// ---------------- DFT over jt on ws slabs (layout-preserving) ---------------
__global__ void k_dft()
{
    const int nh = blockIdx.x, tid = threadIdx.x;
    const __half* slab = g_wsp + (size_t)nh*65536;
    __half* out = g_wc + (size_t)nh*65536;
    #pragma unroll
    for (int it = 0; it < 8; it++) {
        int o4 = tid + it*256;                 // uint2 index 0..2047 in chunk
        float w[8][4];
        #pragma unroll
        for (int jt = 0; jt < 8; jt++) {
            uint2 r = *(const uint2*)(slab + jt*8192 + o4*4);
            __half2 h0 = *(__half2*)&r.x, h1 = *(__half2*)&r.y;
            w[jt][0] = __low2float(h0);  w[jt][1] = __high2float(h0);
            w[jt][2] = __low2float(h1);  w[jt][3] = __high2float(h1);
        }
        #pragma unroll
        for (int c = 0; c < 8; c++) {
            float s[4] = {0,0,0,0};
            #pragma unroll
            for (int jt = 0; jt < 8; jt++) {
                float wgt = DW[c][jt];
                s[0] += wgt*w[jt][0]; s[1] += wgt*w[jt][1];
                s[2] += wgt*w[jt][2]; s[3] += wgt*w[jt][3];
            }
            float sg = (c == 3 || c == 5 || c == 7) ? -1.f : 1.f;  // Wki = -sum sin
            uint2 v;
            v.x = f2h2(sg*s[0], sg*s[1]);
            v.y = f2h2(sg*s[2], sg*s[3]);
            *(uint2*)(out + c*8192 + o4*4) = v;
        }
    }
}

// ---------------- D-hat packed-A panels from alpha --------------------------
__global__ void k_dmat(const float* __restrict__ alpha)
{
    __shared__ float gs[8][1024];
    const int h = blockIdx.x, tid = threadIdx.x;
    for (int i = tid; i < 1024; i += 256) {
        float av[8];
        #pragma unroll
        for (int d = 0; d < 8; d++) av[d] = alpha[h*1024 + ((i + 128*d) & 1023)];
        #pragma unroll
        for (int c = 0; c < 8; c++) {
            float s = 0;
            #pragma unroll
            for (int d = 0; d < 8; d++) s += DW[c][d]*av[d];
            gs[c][i] = s;
        }
    }
    __syncthreads();
    for (int t = 0; t < 28; t++) {
        const float* v = gs[VID[t]];
        float s = SGN[t];
        int cb = (t & 1) * 64;
        #pragma unroll
        for (int it = 0; it < 4; it++) {
            int pos = tid + it*256;
            int k16r = pos >> 8, rt = (pos >> 5) & 7, l = pos & 31;
            int g = l >> 2, tq = l & 3;
            int i0 = rt*16 + g, j0 = cb + k16r*16 + 2*tq;
            uint4 o;
            o.x = f2h2(s*v[(j0 - i0) & 1023],     s*v[(j0 + 1 - i0) & 1023]);
            o.y = f2h2(s*v[(j0 - i0 - 8) & 1023], s*v[(j0 - i0 - 7) & 1023]);
            o.z = f2h2(s*v[(j0 + 8 - i0) & 1023], s*v[(j0 + 9 - i0) & 1023]);
            o.w = o.x;
            *(uint4*)(g_dp + (size_t)h*229376 + t*8192 + k16r*2048 + rt*256 + l*8) = o;
        }
    }
}

// ---------------- GEMM2: 8 products per (h, n-pair), one 28-tile pipeline ---
__global__ __launch_bounds__(256, 2) void k_gemm2()
{
    extern __shared__ __half smh[];
    const int bp = blockIdx.x, h = blockIdx.y;
    const __half* Ap = g_dp + (size_t)h*229376;
    const __half* B0 = g_wc + (size_t)(bp*16 + h)*65536;
    const __half* B1 = g_wc + (size_t)(bp*16 + 8 + h)*65536;
    float* Pb = g_P + (size_t)(bp*8 + h)*8*16384;

    const int tid = threadIdx.x, wid = tid >> 5, lane = tid & 31;
    const int wrt = (wid >> 2) * 4, wnb = (wid & 3) * 4;
    const int wm = (wid >> 2) * 64, wn = (wid & 3) * 32;
    const int gg = lane >> 2, tq = lane & 3;
    float acc[4][4][4] = {};

    auto load_tile = [&](int tt, int buf){
        __half* dA = smh + buf*16384;
        __half* dB = dA + 8192;
        const __half* As = Ap + (size_t)tt*8192;
        #pragma unroll
        for (int i = 0; i < 4; i++) {
            int c = tid + i*256;
            uint32_t dst = smem_u32(dA + c*8);
            asm volatile("cp.async.cg.shared.global [%0], [%1], 16;"
                         :: "r"(dst), "l"(As + c*8));
        }
        int kb = BK16[tt];
        #pragma unroll
        for (int i = 0; i < 4; i++) {
            int c = tid + i*256;
            int k16s = c >> 8, r = c & 255, nb = r >> 4, lp = r & 15;
            const __half* src = ((nb & 8) ? B1 : B0)
                              + (size_t)(kb + k16s)*1024 + (nb & 7)*128 + lp*8;
            uint32_t dst = smem_u32(dB + k16s*2048 + nb*128 + lp*8);
            asm volatile("cp.async.cg.shared.global [%0], [%1], 16;"
                         :: "r"(dst), "l"(src));
        }
        asm volatile("cp.async.commit_group;" ::: "memory");
    };

    load_tile(0, 0);
    load_tile(1, 1);

    for (int tt = 0; tt < 28; tt++) {
        const int cur = tt % 3;
        if (tt + 1 < 28) asm volatile("cp.async.wait_group 1;" ::: "memory");
        else             asm volatile("cp.async.wait_group 0;" ::: "memory");
        __syncthreads();
        if (tt + 2 < 28) load_tile(tt + 2, (tt + 2) % 3);

        const uint4* fA = (const uint4*)(smh + cur*16384);
        const uint2* fB = (const uint2*)(smh + cur*16384 + 8192);
        #pragma unroll
        for (int ks = 0; ks < 4; ks++) {
            uint4 a[4]; uint2 b[4];
            #pragma unroll
            for (int tm = 0; tm < 4; tm++) a[tm] = fA[ks*256 + (wrt + tm)*32 + lane];
            #pragma unroll
            for (int tn = 0; tn < 4; tn++) b[tn] = fB[ks*512 + (wnb + tn)*32 + lane];
            #pragma unroll
            for (int tm = 0; tm < 4; tm++)
                #pragma unroll
                for (int tn = 0; tn < 4; tn++)
                    mma_f16(acc[tm][tn], a[tm], b[tn]);
        }

        int dc = DEND[tt];
        if (dc >= 0) {
            float* d = Pb + (size_t)dc*16384;
            #pragma unroll
            for (int tm = 0; tm < 4; tm++)
                #pragma unroll
                for (int tn = 0; tn < 4; tn++) {
                    int m0 = wm + tm*16 + gg, c0 = wn + tn*8 + 2*tq;
                    *(float2*)(d + (m0    )*128 + c0) = make_float2(acc[tm][tn][0], acc[tm][tn][1]);
                    *(float2*)(d + (m0 + 8)*128 + c0) = make_float2(acc[tm][tn][2], acc[tm][tn][3]);
                    acc[tm][tn][0] = acc[tm][tn][1] = acc[tm][tn][2] = acc[tm][tn][3] = 0.f;
                }
        }
    }
}

// ---------------- Combine: y_pt = sum_c MC[pt][c] P_c -> packed-A y ---------
__global__ void k_cmb()
{
    const int bp = blockIdx.x, h = blockIdx.y, tid = threadIdx.x;
    const float* Pb = g_P + (size_t)(bp*8 + h)*8*16384;
    #pragma unroll
    for (int it = 0; it < 8; it++) {
        int task = tid + it*256;
        int nhalf = task >> 10, rest = task & 1023;
        int k16n = rest >> 8, rt = (rest >> 5) & 7, l = rest & 31;
        int g = l >> 2, tq = l & 3;
        int i0 = rt*16 + g;
        int col = nhalf*64 + k16n*16 + 2*tq;

        float y[8][8];
        #pragma unroll
        for (int pt = 0; pt < 8; pt++)
            #pragma unroll
            for (int q = 0; q < 8; q++) y[pt][q] = 0.f;

        #pragma unroll
        for (int c = 0; c < 8; c++) {
            const float* base = Pb + (size_t)c*16384;
            float2 a0 = *(const float2*)(base + (i0    )*128 + col);
            float2 a1 = *(const float2*)(base + (i0 + 8)*128 + col);
            float2 a2 = *(const float2*)(base + (i0    )*128 + col + 8);
            float2 a3 = *(const float2*)(base + (i0 + 8)*128 + col + 8);
            #pragma unroll
            for (int pt = 0; pt < 8; pt++) {
                float m = MC[pt][c];
                y[pt][0] += m*a0.x; y[pt][1] += m*a0.y;
                y[pt][2] += m*a1.x; y[pt][3] += m*a1.y;
                y[pt][4] += m*a2.x; y[pt][5] += m*a2.y;
                y[pt][6] += m*a3.x; y[pt][7] += m*a3.y;
            }
        }
        #pragma unroll
        for (int pt = 0; pt < 8; pt++) {
            uint4 v;
            v.x = f2h2(y[pt][0], y[pt][1]);
            v.y = f2h2(y[pt][2], y[pt][3]);
            v.z = f2h2(y[pt][4], y[pt][5]);
            v.w = f2h2(y[pt][6], y[pt][7]);
            int panel = (bp*2 + nhalf)*8 + pt;
            *(uint4*)(g_yp + (size_t)panel*65536 + (h*4 + k16n)*2048 + rt*256 + l*8) = v;
        }
    }
}

// ---------------- Stage 3: out = log_cosh(y @ W + b) ------------------------
__global__ __launch_bounds__(256, 2) void k_stage3(const float* __restrict__ bias,
                                                   float* __restrict__ out)
{
    extern __shared__ __half smh[];
    const int bn = blockIdx.x * 128, bm = blockIdx.y * 128;
    float acc[4][4][4] = {};
    const __half* b0 = g_wp + (bn >> 3) * 128;
    gemm_loop(g_yp + (size_t)(bm >> 7)*65536, b0, b0 + 1024, 8192, 8, smh, acc);

    const int tid = threadIdx.x, wid = tid >> 5, lane = tid & 31;
    const int wm = (wid >> 2) * 64, wn = (wid & 3) * 32;
    const int gg = lane >> 2, tq = lane & 3;
    #pragma unroll
    for (int tn = 0; tn < 4; tn++) {
        int n0 = wn + tn*8 + 2*tq;
        float bb0 = bias[bn + n0], bb1 = bias[bn + n0 + 1];
        #pragma unroll
        for (int tm = 0; tm < 4; tm++) {
            int m0 = bm + wm + tm*16 + gg;
            float2 v0 = make_float2(log_cosh_f(acc[tm][tn][0] + bb0),
                                    log_cosh_f(acc[tm][tn][1] + bb1));
            float2 v1 = make_float2(log_cosh_f(acc[tm][tn][2] + bb0),
                                    log_cosh_f(acc[tm][tn][3] + bb1));
            *(float2*)(out + (size_t)(m0    )*EE_ + bn + n0) = v0;
            *(float2*)(out + (size_t)(m0 + 8)*EE_ + bn + n0) = v1;
        }
    }
}

// ---------------- pack kernels ----------------------------------------------
__global__ void k_pack_x(const float* __restrict__ x)
{
    __shared__ float S[128*68];
    const int panel = blockIdx.x, kslab = blockIdx.y;
    const int tid = threadIdx.x;
    #pragma unroll
    for (int i = 0; i < 8; i++) {
        int c = tid + i*256, row = c >> 4, seg = c & 15;
        float4 v = *(const float4*)(x + (size_t)(panel*128 + row)*512 + kslab*64 + seg*4);
        *(float4*)(S + row*68 + seg*4) = v;
    }
    __syncthreads();
    #pragma unroll
    for (int i = 0; i < 4; i++) {
        int u = tid + i*256;
        int k16 = u >> 8, rt = (u >> 5) & 7, l = u & 31;
        int g = l >> 2, t = l & 3;
        const float* s0 = S + (rt*16 + g)*68 + k16*16 + 2*t;
        const float* s1 = s0 + 8*68;
        uint4 v;
        v.x = f2h2(s0[0], s0[1]); v.y = f2h2(s1[0], s1[1]);
        v.z = f2h2(s0[8], s0[9]); v.w = f2h2(s1[8], s1[9]);
        *(uint4*)(g_xa + (size_t)panel*65536 + (size_t)(kslab*4 + k16)*2048
                  + rt*256 + l*8) = v;
    }
}

__global__ void k_pack_v(const float* __restrict__ V)
{
    int k16 = blockIdx.x, nb = blockIdx.y*8 + (threadIdx.x >> 5), l = threadIdx.x & 31;
    int g = l >> 2, t = l & 3;
    const float* r = V + (size_t)(nb*8 + g)*512 + k16*16 + 2*t;
    uint2 v;
    v.x = f2h2(r[0], r[1]); v.y = f2h2(r[8], r[9]);
    *(uint2*)(g_vp + k16*8192 + nb*128 + l*4) = v;
}

__global__ void k_pack_w(const float* __restrict__ W)
{
    int k16 = blockIdx.x, nb = blockIdx.y*8 + (threadIdx.x >> 5), l = threadIdx.x & 31;
    int g = l >> 2, t = l & 3;
    int e = nb*8 + g, k = k16*16 + 2*t;
    uint2 v;
    v.x = f2h2(W[(size_t)(k    )*512 + e], W[(size_t)(k + 1)*512 + e]);
    v.y = f2h2(W[(size_t)(k + 8)*512 + e], W[(size_t)(k + 9)*512 + e]);
    *(uint2*)(g_wp + k16*8192 + nb*128 + l*4) = v;
}

// ---------------------------------------------------------------------------
extern "C" void kernel_launch(void* const* d_in, const int* in_sizes, int n_in,
                              void* d_out, int out_size)
{
    const float* x     = (const float*)d_in[0];
    const float* alpha = (const float*)d_in[1];
    const float* V     = (const float*)d_in[2];
    const float* W     = (const float*)d_in[3];
    const float* b     = (const float*)d_in[4];
    float* out = (float*)d_out;

    cudaFuncSetAttribute(k_stage1, cudaFuncAttributeMaxDynamicSharedMemorySize, SMEM_BYTES);
    cudaFuncSetAttribute(k_gemm2, cudaFuncAttributeMaxDynamicSharedMemorySize, SMEM_BYTES);
    cudaFuncSetAttribute(k_stage3, cudaFuncAttributeMaxDynamicSharedMemorySize, SMEM_BYTES);

    k_pack_x<<<dim3(512, 8), 256>>>(x);
    k_pack_v<<<dim3(32, 8),  256>>>(V);
    k_pack_w<<<dim3(32, 8),  256>>>(W);
    k_dmat  <<<8, 256>>>(alpha);

    k_stage1<<<dim3(4, 512), 256, SMEM_BYTES>>>();
    k_dft   <<<512, 256>>>();
    k_gemm2 <<<dim3(32, 8), 256, SMEM_BYTES>>>();
    k_cmb   <<<dim3(32, 8), 256>>>();
    k_stage3<<<dim3(4, 512), 256, SMEM_BYTES>>>(b, out);
}

// round 13
// speedup vs baseline: 1.1747x; 1.0367x over previous
#include <cuda_runtime.h>
#include <cuda_fp16.h>
#include <cstdint>
#include <math.h>

#define NN_ 64
#define PP_ 1024
#define EE_ 512
#define HH_ 8
#define MBIG (NN_*PP_)

#define SMEM_BYTES 98304   // 3 stages x (A 8192 + B 8192 halfs)

// ---------------- scratch ---------------------------------------------------
__device__ __half g_xa [(size_t)512*65536];   // x packed-A
__device__ __half g_vp [(size_t)EE_*EE_];     // V packed-B
__device__ __half g_wp [(size_t)EE_*EE_];     // W^T packed-B
__device__ __half g_wsp[(size_t)512*65536];   // ws packed-B per (n,h)
__device__ __half g_wc [(size_t)512*65536];   // W-hat slabs per (n,h)
__device__ __half g_dp [(size_t)8*229376];    // D-hat packed-A panels per h
__device__ __half g_Ph [(size_t)256*8*16384]; // products fp16 [(bp*8+h)][c][i][col]
__device__ __half g_yp [(size_t)512*65536];   // y packed-A

// DFT weight rows: {1, (-1)^d, cos(pi d/4), sin(pi d/4), cos(pi d/2), sin(pi d/2), cos(3pi d/4), sin(3pi d/4)}
#define C7 0.70710678118654752f
__constant__ float DW[8][8] = {
 {1,1,1,1,1,1,1,1}, {1,-1,1,-1,1,-1,1,-1},
 {1,C7,0,-C7,-1,-C7,0,C7}, {0,C7,1,C7,0,-C7,-1,-C7},
 {1,0,-1,0,1,0,-1,0}, {0,1,0,-1,0,1,0,-1},
 {1,-C7,0,C7,-1,C7,0,-C7}, {0,C7,-1,C7,0,-C7,1,-C7}};
// combine: y_pt = sum_c MC[pt][c] * P_c ; comps {P0,P4,P1r,P1i,P2r,P2i,P3r,P3i}
#define Q 0.17677669529663687f
__constant__ float MC[8][8] = {
 {.125f,.125f,.25f,0,.25f,0,.25f,0},
 {.125f,-.125f,Q,-Q,0,-.25f,-Q,-Q},
 {.125f,.125f,0,-.25f,-.25f,0,0,.25f},
 {.125f,-.125f,-Q,-Q,0,.25f,Q,-Q},
 {.125f,.125f,-.25f,0,.25f,0,-.25f,0},
 {.125f,-.125f,-Q,Q,0,-.25f,Q,Q},
 {.125f,.125f,0,.25f,-.25f,0,0,-.25f},
 {.125f,-.125f,Q,Q,0,.25f,-Q,Q}};
__constant__ int BK16[28] = {0,4,8,12,16,20,24,28,16,20,24,28,
                             32,36,40,44,32,36,40,44,48,52,56,60,48,52,56,60};
__constant__ int DEND[28] = {-1,0,-1,1,-1,-1,-1,2,-1,-1,-1,3,
                             -1,-1,-1,4,-1,-1,-1,5,-1,-1,-1,6,-1,-1,-1,7};
__constant__ int VID[28]  = {0,0,1,1,2,2,3,3,3,3,2,2,4,4,5,5,5,5,4,4,6,6,7,7,7,7,6,6};
__constant__ float SGN[28]= {1,1,1,1,1,1,-1,-1,1,1,1,1,1,1,-1,-1,1,1,1,1,1,1,-1,-1,1,1,1,1};

// ---------------- helpers ---------------------------------------------------
__device__ __forceinline__ uint32_t smem_u32(const void* p){
    uint32_t a;
    asm("{ .reg .u64 t; cvta.to.shared.u64 t, %1; cvt.u32.u64 %0, t; }":"=r"(a):"l"(p));
    return a;
}
__device__ __forceinline__ uint32_t f2h2(float a, float b){
    __half2 h = __floats2half2_rn(a, b);
    return *(uint32_t*)&h;
}
__device__ __forceinline__ float log_cosh_f(float v){
    float ax = fabsf(v);
    return ax + log1pf(expf(-2.0f*ax)) - 0.6931471805599453f;
}
__device__ __forceinline__ void mma_f16(float c[4], uint4 a, uint2 b)
{
    asm volatile("mma.sync.aligned.m16n8k16.row.col.f32.f16.f16.f32 "
        "{%0,%1,%2,%3}, {%4,%5,%6,%7}, {%8,%9}, {%0,%1,%2,%3};"
        : "+f"(c[0]), "+f"(c[1]), "+f"(c[2]), "+f"(c[3])
        : "r"(a.x), "r"(a.y), "r"(a.z), "r"(a.w), "r"(b.x), "r"(b.y));
}

// ---------------- shared mainloop for stages 1/3 ----------------------------
__device__ __forceinline__ void gemm_loop(
    const __half* __restrict__ Ap,
    const __half* __restrict__ B0, const __half* __restrict__ B1,
    size_t bstride, int kt, __half* __restrict__ sm, float acc[4][4][4])
{
    const int tid = threadIdx.x, wid = tid >> 5, lane = tid & 31;
    const int wrt = (wid >> 2) * 4, wnb = (wid & 3) * 4;

    auto load_tile = [&](int tt, int buf){
        __half* dA = sm + buf*16384;
        __half* dB = dA + 8192;
        const __half* As = Ap + (size_t)tt*8192;
        #pragma unroll
        for (int i = 0; i < 4; i++) {
            int c = tid + i*256;
            uint32_t dst = smem_u32(dA + c*8);
            asm volatile("cp.async.cg.shared.global [%0], [%1], 16;"
                         :: "r"(dst), "l"(As + c*8));
        }
        #pragma unroll
        for (int i = 0; i < 4; i++) {
            int c = tid + i*256;
            int k16s = c >> 8, r = c & 255, nb = r >> 4, lp = r & 15;
            const __half* src = ((nb & 8) ? B1 : B0)
                              + (size_t)(tt*4 + k16s)*bstride + (nb & 7)*128 + lp*8;
            uint32_t dst = smem_u32(dB + k16s*2048 + nb*128 + lp*8);
            asm volatile("cp.async.cg.shared.global [%0], [%1], 16;"
                         :: "r"(dst), "l"(src));
        }
        asm volatile("cp.async.commit_group;" ::: "memory");
    };

    load_tile(0, 0);
    if (kt > 1) load_tile(1, 1);

    for (int tt = 0; tt < kt; tt++) {
        const int cur = tt % 3;
        if (tt + 1 < kt) asm volatile("cp.async.wait_group 1;" ::: "memory");
        else             asm volatile("cp.async.wait_group 0;" ::: "memory");
        __syncthreads();
        if (tt + 2 < kt) load_tile(tt + 2, (tt + 2) % 3);

        const uint4* fA = (const uint4*)(sm + cur*16384);
        const uint2* fB = (const uint2*)(sm + cur*16384 + 8192);
        #pragma unroll
        for (int ks = 0; ks < 4; ks++) {
            uint4 a[4]; uint2 b[4];
            #pragma unroll
            for (int tm = 0; tm < 4; tm++) a[tm] = fA[ks*256 + (wrt + tm)*32 + lane];
            #pragma unroll
            for (int tn = 0; tn < 4; tn++) b[tn] = fB[ks*512 + (wnb + tn)*32 + lane];
            #pragma unroll
            for (int tm = 0; tm < 4; tm++)
                #pragma unroll
                for (int tn = 0; tn < 4; tn++)
                    mma_f16(acc[tm][tn], a[tm], b[tn]);
        }
    }
}

// ---------------- Stage 1: ws = x @ V^T -> packed-B slabs -------------------
__global__ __launch_bounds__(256, 2) void k_stage1()
{
    extern __shared__ __half smh[];
    const int bn = blockIdx.x * 128, bm = blockIdx.y * 128;
    float acc[4][4][4] = {};
    const __half* b0 = g_vp + (bn >> 3) * 128;
    gemm_loop(g_xa + (size_t)(bm >> 7)*65536, b0, b0 + 1024, 8192, 8, smh, acc);

    __syncthreads();
    float* Ts = (float*)smh;
    const int tid = threadIdx.x, wid = tid >> 5, lane = tid & 31;
    const int wm = (wid >> 2) * 64, wn = (wid & 3) * 32;
    const int gg = lane >> 2, tq = lane & 3;
    #pragma unroll
    for (int tm = 0; tm < 4; tm++)
        #pragma unroll
        for (int tn = 0; tn < 4; tn++) {
            int m0 = wm + tm*16 + gg, n0 = wn + tn*8 + 2*tq;
            Ts[(n0    )*132 + m0    ] = acc[tm][tn][0];
            Ts[(n0 + 1)*132 + m0    ] = acc[tm][tn][1];
            Ts[(n0    )*132 + m0 + 8] = acc[tm][tn][2];
            Ts[(n0 + 1)*132 + m0 + 8] = acc[tm][tn][3];
        }
    __syncthreads();

    const int n = bm >> 10, pbase = bm & 1023;
    #pragma unroll
    for (int i = 0; i < 16; i++) {
        int u = tid + i*256;
        int k16rel = u >> 9, rest = u & 511;
        int nbg = rest >> 5, l = rest & 31, g = l >> 2, t = l & 3;
        int hrloc = nbg*8 + g, hrAbs = bn + hrloc;
        const float* ts = Ts + hrloc*132 + k16rel*16 + 2*t;
        uint2 v;
        v.x = f2h2(ts[0], ts[1]);
        v.y = f2h2(ts[8], ts[9]);
        size_t dst = (size_t)(n*8 + (hrAbs >> 6))*65536
                   + (size_t)((pbase >> 4) + k16rel)*1024
                   + ((hrAbs >> 3) & 7)*128 + l*4;
        *(uint2*)(g_wsp + dst) = v;
    }
}

// ---------------- DFT over jt on ws slabs (layout-preserving) ---------------
__global__ void k_dft()
{
    const int nh = blockIdx.x, tid = threadIdx.x;
    const __half* slab = g_wsp + (size_t)nh*65536;
    __half* out = g_wc + (size_t)nh*65536;
    #pragma unroll
    for (int it = 0; it < 8; it++) {
        int o4 = tid + it*256;
        float w[8][4];
        #pragma unroll
        for (int jt = 0; jt < 8; jt++) {
            uint2 r = *(const uint2*)(slab + jt*8192 + o4*4);
            __half2 h0 = *(__half2*)&r.x, h1 = *(__half2*)&r.y;
            w[jt][0] = __low2float(h0);  w[jt][1] = __high2float(h0);
            w[jt][2] = __low2float(h1);  w[jt][3] = __high2float(h1);
        }
        #pragma unroll
        for (int c = 0; c < 8; c++) {
            float s[4] = {0,0,0,0};
            #pragma unroll
            for (int jt = 0; jt < 8; jt++) {
                float wgt = DW[c][jt];
                s[0] += wgt*w[jt][0]; s[1] += wgt*w[jt][1];
                s[2] += wgt*w[jt][2]; s[3] += wgt*w[jt][3];
            }
            float sg = (c == 3 || c == 5 || c == 7) ? -1.f : 1.f;
            uint2 v;
            v.x = f2h2(sg*s[0], sg*s[1]);
            v.y = f2h2(sg*s[2], sg*s[3]);
            *(uint2*)(out + c*8192 + o4*4) = v;
        }
    }
}

// ---------------- D-hat packed-A panels from alpha --------------------------
// grid (8 h, 7 tile-groups of 4) — parallelized
__global__ void k_dmat(const float* __restrict__ alpha)
{
    __shared__ float gs[8][1024];
    const int h = blockIdx.x, tg = blockIdx.y, tid = threadIdx.x;
    for (int i = tid; i < 1024; i += 256) {
        float av[8];
        #pragma unroll
        for (int d = 0; d < 8; d++) av[d] = alpha[h*1024 + ((i + 128*d) & 1023)];
        #pragma unroll
        for (int c = 0; c < 8; c++) {
            float s = 0;
            #pragma unroll
            for (int d = 0; d < 8; d++) s += DW[c][d]*av[d];
            gs[c][i] = s;
        }
    }
    __syncthreads();
    #pragma unroll
    for (int tl = 0; tl < 4; tl++) {
        int t = tg*4 + tl;
        const float* v = gs[VID[t]];
        float s = SGN[t];
        int cb = (t & 1) * 64;
        #pragma unroll
        for (int it = 0; it < 4; it++) {
            int pos = tid + it*256;
            int k16r = pos >> 8, rt = (pos >> 5) & 7, l = pos & 31;
            int g = l >> 2, tq = l & 3;
            int i0 = rt*16 + g, j0 = cb + k16r*16 + 2*tq;
            uint4 o;
            o.x = f2h2(s*v[(j0 - i0) & 1023],     s*v[(j0 + 1 - i0) & 1023]);
            o.y = f2h2(s*v[(j0 - i0 - 8) & 1023], s*v[(j0 - i0 - 7) & 1023]);
            o.z = f2h2(s*v[(j0 + 8 - i0) & 1023], s*v[(j0 + 9 - i0) & 1023]);
            o.w = o.x;
            *(uint4*)(g_dp + (size_t)h*229376 + t*8192 + k16r*2048 + rt*256 + l*8) = o;
        }
    }
}

// ---------------- GEMM2: 8 products per (h, n-pair), one 28-tile pipeline ---
__global__ __launch_bounds__(256, 2) void k_gemm2()
{
    extern __shared__ __half smh[];
    const int bp = blockIdx.x, h = blockIdx.y;
    const __half* Ap = g_dp + (size_t)h*229376;
    const __half* B0 = g_wc + (size_t)(bp*16 + h)*65536;
    const __half* B1 = g_wc + (size_t)(bp*16 + 8 + h)*65536;
    __half* Pb = g_Ph + (size_t)(bp*8 + h)*8*16384;

    const int tid = threadIdx.x, wid = tid >> 5, lane = tid & 31;
    const int wrt = (wid >> 2) * 4, wnb = (wid & 3) * 4;
    const int wm = (wid >> 2) * 64, wn = (wid & 3) * 32;
    const int gg = lane >> 2, tq = lane & 3;
    float acc[4][4][4] = {};

    auto load_tile = [&](int tt, int buf){
        __half* dA = smh + buf*16384;
        __half* dB = dA + 8192;
        const __half* As = Ap + (size_t)tt*8192;
        #pragma unroll
        for (int i = 0; i < 4; i++) {
            int c = tid + i*256;
            uint32_t dst = smem_u32(dA + c*8);
            asm volatile("cp.async.cg.shared.global [%0], [%1], 16;"
                         :: "r"(dst), "l"(As + c*8));
        }
        int kb = BK16[tt];
        #pragma unroll
        for (int i = 0; i < 4; i++) {
            int c = tid + i*256;
            int k16s = c >> 8, r = c & 255, nb = r >> 4, lp = r & 15;
            const __half* src = ((nb & 8) ? B1 : B0)
                              + (size_t)(kb + k16s)*1024 + (nb & 7)*128 + lp*8;
            uint32_t dst = smem_u32(dB + k16s*2048 + nb*128 + lp*8);
            asm volatile("cp.async.cg.shared.global [%0], [%1], 16;"
                         :: "r"(dst), "l"(src));
        }
        asm volatile("cp.async.commit_group;" ::: "memory");
    };

    load_tile(0, 0);
    load_tile(1, 1);

    for (int tt = 0; tt < 28; tt++) {
        const int cur = tt % 3;
        if (tt + 1 < 28) asm volatile("cp.async.wait_group 1;" ::: "memory");
        else             asm volatile("cp.async.wait_group 0;" ::: "memory");
        __syncthreads();
        if (tt + 2 < 28) load_tile(tt + 2, (tt + 2) % 3);

        const uint4* fA = (const uint4*)(smh + cur*16384);
        const uint2* fB = (const uint2*)(smh + cur*16384 + 8192);
        #pragma unroll
        for (int ks = 0; ks < 4; ks++) {
            uint4 a[4]; uint2 b[4];
            #pragma unroll
            for (int tm = 0; tm < 4; tm++) a[tm] = fA[ks*256 + (wrt + tm)*32 + lane];
            #pragma unroll
            for (int tn = 0; tn < 4; tn++) b[tn] = fB[ks*512 + (wnb + tn)*32 + lane];
            #pragma unroll
            for (int tm = 0; tm < 4; tm++)
                #pragma unroll
                for (int tn = 0; tn < 4; tn++)
                    mma_f16(acc[tm][tn], a[tm], b[tn]);
        }

        int dc = DEND[tt];
        if (dc >= 0) {
            __half* d = Pb + (size_t)dc*16384;
            #pragma unroll
            for (int tm = 0; tm < 4; tm++)
                #pragma unroll
                for (int tn = 0; tn < 4; tn++) {
                    int m0 = wm + tm*16 + gg, c0 = wn + tn*8 + 2*tq;
                    *(uint32_t*)(d + (m0    )*128 + c0) = f2h2(acc[tm][tn][0], acc[tm][tn][1]);
                    *(uint32_t*)(d + (m0 + 8)*128 + c0) = f2h2(acc[tm][tn][2], acc[tm][tn][3]);
                    acc[tm][tn][0] = acc[tm][tn][1] = acc[tm][tn][2] = acc[tm][tn][3] = 0.f;
                }
        }
    }
}

// ---------------- Combine: y_pt = sum_c MC[pt][c] P_c -> packed-A y ---------
__global__ void k_cmb()
{
    const int bp = blockIdx.x, h = blockIdx.y, tid = threadIdx.x;
    const __half* Pb = g_Ph + (size_t)(bp*8 + h)*8*16384;
    #pragma unroll
    for (int it = 0; it < 8; it++) {
        int task = tid + it*256;
        int nhalf = task >> 10, rest = task & 1023;
        int k16n = rest >> 8, rt = (rest >> 5) & 7, l = rest & 31;
        int g = l >> 2, tq = l & 3;
        int i0 = rt*16 + g;
        int col = nhalf*64 + k16n*16 + 2*tq;

        float y[8][8];
        #pragma unroll
        for (int pt = 0; pt < 8; pt++)
            #pragma unroll
            for (int q = 0; q < 8; q++) y[pt][q] = 0.f;

        #pragma unroll
        for (int c = 0; c < 8; c++) {
            const __half* base = Pb + (size_t)c*16384;
            __half2 a0 = *(const __half2*)(base + (i0    )*128 + col);
            __half2 a1 = *(const __half2*)(base + (i0 + 8)*128 + col);
            __half2 a2 = *(const __half2*)(base + (i0    )*128 + col + 8);
            __half2 a3 = *(const __half2*)(base + (i0 + 8)*128 + col + 8);
            float f0x = __low2float(a0), f0y = __high2float(a0);
            float f1x = __low2float(a1), f1y = __high2float(a1);
            float f2x = __low2float(a2), f2y = __high2float(a2);
            float f3x = __low2float(a3), f3y = __high2float(a3);
            #pragma unroll
            for (int pt = 0; pt < 8; pt++) {
                float m = MC[pt][c];
                y[pt][0] += m*f0x; y[pt][1] += m*f0y;
                y[pt][2] += m*f1x; y[pt][3] += m*f1y;
                y[pt][4] += m*f2x; y[pt][5] += m*f2y;
                y[pt][6] += m*f3x; y[pt][7] += m*f3y;
            }
        }
        #pragma unroll
        for (int pt = 0; pt < 8; pt++) {
            uint4 v;
            v.x = f2h2(y[pt][0], y[pt][1]);
            v.y = f2h2(y[pt][2], y[pt][3]);
            v.z = f2h2(y[pt][4], y[pt][5]);
            v.w = f2h2(y[pt][6], y[pt][7]);
            int panel = (bp*2 + nhalf)*8 + pt;
            *(uint4*)(g_yp + (size_t)panel*65536 + (h*4 + k16n)*2048 + rt*256 + l*8) = v;
        }
    }
}

// ---------------- Stage 3: out = log_cosh(y @ W + b) ------------------------
__global__ __launch_bounds__(256, 2) void k_stage3(const float* __restrict__ bias,
                                                   float* __restrict__ out)
{
    extern __shared__ __half smh[];
    const int bn = blockIdx.x * 128, bm = blockIdx.y * 128;
    float acc[4][4][4] = {};
    const __half* b0 = g_wp + (bn >> 3) * 128;
    gemm_loop(g_yp + (size_t)(bm >> 7)*65536, b0, b0 + 1024, 8192, 8, smh, acc);

    const int tid = threadIdx.x, wid = tid >> 5, lane = tid & 31;
    const int wm = (wid >> 2) * 64, wn = (wid & 3) * 32;
    const int gg = lane >> 2, tq = lane & 3;
    #pragma unroll
    for (int tn = 0; tn < 4; tn++) {
        int n0 = wn + tn*8 + 2*tq;
        float bb0 = bias[bn + n0], bb1 = bias[bn + n0 + 1];
        #pragma unroll
        for (int tm = 0; tm < 4; tm++) {
            int m0 = bm + wm + tm*16 + gg;
            float2 v0 = make_float2(log_cosh_f(acc[tm][tn][0] + bb0),
                                    log_cosh_f(acc[tm][tn][1] + bb1));
            float2 v1 = make_float2(log_cosh_f(acc[tm][tn][2] + bb0),
                                    log_cosh_f(acc[tm][tn][3] + bb1));
            *(float2*)(out + (size_t)(m0    )*EE_ + bn + n0) = v0;
            *(float2*)(out + (size_t)(m0 + 8)*EE_ + bn + n0) = v1;
        }
    }
}

// ---------------- pack kernels ----------------------------------------------
__global__ void k_pack_x(const float* __restrict__ x)
{
    __shared__ float S[128*68];
    const int panel = blockIdx.x, kslab = blockIdx.y;
    const int tid = threadIdx.x;
    #pragma unroll
    for (int i = 0; i < 8; i++) {
        int c = tid + i*256, row = c >> 4, seg = c & 15;
        float4 v = *(const float4*)(x + (size_t)(panel*128 + row)*512 + kslab*64 + seg*4);
        *(float4*)(S + row*68 + seg*4) = v;
    }
    __syncthreads();
    #pragma unroll
    for (int i = 0; i < 4; i++) {
        int u = tid + i*256;
        int k16 = u >> 8, rt = (u >> 5) & 7, l = u & 31;
        int g = l >> 2, t = l & 3;
        const float* s0 = S + (rt*16 + g)*68 + k16*16 + 2*t;
        const float* s1 = s0 + 8*68;
        uint4 v;
        v.x = f2h2(s0[0], s0[1]); v.y = f2h2(s1[0], s1[1]);
        v.z = f2h2(s0[8], s0[9]); v.w = f2h2(s1[8], s1[9]);
        *(uint4*)(g_xa + (size_t)panel*65536 + (size_t)(kslab*4 + k16)*2048
                  + rt*256 + l*8) = v;
    }
}

__global__ void k_pack_v(const float* __restrict__ V)
{
    int k16 = blockIdx.x, nb = blockIdx.y*8 + (threadIdx.x >> 5), l = threadIdx.x & 31;
    int g = l >> 2, t = l & 3;
    const float* r = V + (size_t)(nb*8 + g)*512 + k16*16 + 2*t;
    uint2 v;
    v.x = f2h2(r[0], r[1]); v.y = f2h2(r[8], r[9]);
    *(uint2*)(g_vp + k16*8192 + nb*128 + l*4) = v;
}

__global__ void k_pack_w(const float* __restrict__ W)
{
    int k16 = blockIdx.x, nb = blockIdx.y*8 + (threadIdx.x >> 5), l = threadIdx.x & 31;
    int g = l >> 2, t = l & 3;
    int e = nb*8 + g, k = k16*16 + 2*t;
    uint2 v;
    v.x = f2h2(W[(size_t)(k    )*512 + e], W[(size_t)(k + 1)*512 + e]);
    v.y = f2h2(W[(size_t)(k + 8)*512 + e], W[(size_t)(k + 9)*512 + e]);
    *(uint2*)(g_wp + k16*8192 + nb*128 + l*4) = v;
}

// ---------------------------------------------------------------------------
extern "C" void kernel_launch(void* const* d_in, const int* in_sizes, int n_in,
                              void* d_out, int out_size)
{
    const float* x     = (const float*)d_in[0];
    const float* alpha = (const float*)d_in[1];
    const float* V     = (const float*)d_in[2];
    const float* W     = (const float*)d_in[3];
    const float* b     = (const float*)d_in[4];
    float* out = (float*)d_out;

    cudaFuncSetAttribute(k_stage1, cudaFuncAttributeMaxDynamicSharedMemorySize, SMEM_BYTES);
    cudaFuncSetAttribute(k_gemm2, cudaFuncAttributeMaxDynamicSharedMemorySize, SMEM_BYTES);
    cudaFuncSetAttribute(k_stage3, cudaFuncAttributeMaxDynamicSharedMemorySize, SMEM_BYTES);

    k_pack_x<<<dim3(512, 8), 256>>>(x);
    k_pack_v<<<dim3(32, 8),  256>>>(V);
    k_pack_w<<<dim3(32, 8),  256>>>(W);
    k_dmat  <<<dim3(8, 7), 256>>>(alpha);

    k_stage1<<<dim3(4, 512), 256, SMEM_BYTES>>>();
    k_dft   <<<512, 256>>>();
    k_gemm2 <<<dim3(32, 8), 256, SMEM_BYTES>>>();
    k_cmb   <<<dim3(32, 8), 256>>>();
    k_stage3<<<dim3(4, 512), 256, SMEM_BYTES>>>(b, out);
}